// round 6
// baseline (speedup 1.0000x reference)
#include <cuda_runtime.h>
#include <cuda_fp16.h>
#include <math.h>
#include <stdint.h>

#define RTOT 65536
#define CD   768
#define EPS  1e-5f
#define NCHUNK 8   // m-blocks per CTA in the weight-stationary GEMM

// ---------------- scratch (static __device__, allocation-free) --------------
__device__ __half g_xh  [RTOT*CD];  // LN1 out (windowed order), fp16
__device__ __half g_qinh[RTOT*CD];  // green+blue
__device__ __half g_kinh[RTOT*CD];  // red
__device__ __half g_qh  [RTOT*CD];
__device__ __half g_kh  [RTOT*CD];
__device__ __half g_vh  [RTOT*CD];
__device__ __half g_ath [RTOT*CD];  // attention out
__device__ float  g_a   [RTOT*CD];  // proj out (fp32 for LN2 accuracy)
__device__ __half g_wh  [4*589824]; // fp16 weights: Wq,Wk,Wv,Wp

// ---------------- helpers ---------------------------------------------------
__device__ __forceinline__ void cp16(void* dst, const void* src) {
    unsigned d = (unsigned)__cvta_generic_to_shared(dst);
    asm volatile("cp.async.cg.shared.global [%0], [%1], 16;\n" :: "r"(d), "l"(src));
}
__device__ __forceinline__ void ldsm4(unsigned &r0, unsigned &r1, unsigned &r2, unsigned &r3, unsigned a) {
    asm volatile("ldmatrix.sync.aligned.m8n8.x4.shared.b16 {%0,%1,%2,%3}, [%4];"
                 : "=r"(r0), "=r"(r1), "=r"(r2), "=r"(r3) : "r"(a));
}
__device__ __forceinline__ void ldsm4t(unsigned &r0, unsigned &r1, unsigned &r2, unsigned &r3, unsigned a) {
    asm volatile("ldmatrix.sync.aligned.m8n8.x4.trans.shared.b16 {%0,%1,%2,%3}, [%4];"
                 : "=r"(r0), "=r"(r1), "=r"(r2), "=r"(r3) : "r"(a));
}
__device__ __forceinline__ void mma16816(float* c, const unsigned* a, const unsigned* b) {
    asm volatile(
        "mma.sync.aligned.m16n8k16.row.col.f32.f16.f16.f32 "
        "{%0,%1,%2,%3}, {%4,%5,%6,%7}, {%8,%9}, {%0,%1,%2,%3};\n"
        : "+f"(c[0]), "+f"(c[1]), "+f"(c[2]), "+f"(c[3])
        : "r"(a[0]), "r"(a[1]), "r"(a[2]), "r"(a[3]), "r"(b[0]), "r"(b[1]));
}
__device__ __forceinline__ unsigned packh2(float x, float y) {
    __half2 h = __floats2half2_rn(x, y);
    return *reinterpret_cast<unsigned*>(&h);
}
__device__ __forceinline__ uint32_t s2u(const void* p) {
    return (uint32_t)__cvta_generic_to_shared(p);
}

// ---------------------------------------------------------------------------
// Kernel 0: weights fp32 -> fp16
// ---------------------------------------------------------------------------
__global__ void k_w2h(const float* __restrict__ qkv, const float* __restrict__ proj) {
    int i = blockIdx.x * 256 + threadIdx.x;
    float v = (i < 1769472) ? qkv[i] : proj[i - 1769472];
    g_wh[i] = __float2half_rn(v);
}

// ---------------------------------------------------------------------------
// Kernel 1: LN1 fused with window partition -> fp16 windowed rows
// ---------------------------------------------------------------------------
__global__ void k_ln1(const float* __restrict__ x,
                      const float* __restrict__ g,
                      const float* __restrict__ b) {
    int wr  = blockIdx.x;
    int win = wr >> 6, t = wr & 63;
    int bb  = win >> 8, rem = win & 255;
    int wh  = rem >> 4, ww = rem & 15;
    int ii  = t >> 3,  jj = t & 7;
    int sr  = bb * 16384 + (wh * 8 + ii) * 128 + ww * 8 + jj;

    const float* xr = x + (size_t)sr * CD;
    int tid = threadIdx.x;
    float v0 = xr[tid], v1 = xr[tid + 256], v2 = xr[tid + 512];
    float ls = v0 + v1 + v2;
    float lq = v0*v0 + v1*v1 + v2*v2;
    #pragma unroll
    for (int o = 16; o > 0; o >>= 1) {
        ls += __shfl_xor_sync(0xffffffffu, ls, o);
        lq += __shfl_xor_sync(0xffffffffu, lq, o);
    }
    __shared__ float ss[8], sq[8];
    int wid = tid >> 5;
    if ((tid & 31) == 0) { ss[wid] = ls; sq[wid] = lq; }
    __syncthreads();
    float S = 0.f, Q = 0.f;
    #pragma unroll
    for (int k = 0; k < 8; k++) { S += ss[k]; Q += sq[k]; }
    float m   = S * (1.f / 768.f);
    float var = Q * (1.f / 768.f) - m * m;
    float inv = rsqrtf(var + EPS);

    __half* o = g_xh + (size_t)wr * CD;
    o[tid      ] = __float2half_rn((v0 - m) * inv * g[tid      ] + b[tid      ]);
    o[tid + 256] = __float2half_rn((v1 - m) * inv * g[tid + 256] + b[tid + 256]);
    o[tid + 512] = __float2half_rn((v2 - m) * inv * g[tid + 512] + b[tid + 512]);
}

// ---------------------------------------------------------------------------
// Kernel 2: reshape(3,..)/tile shuffle. kin = red, qin = green + blue.
// ---------------------------------------------------------------------------
__global__ void k_gather() {
    int r   = blockIdx.x;
    int tid = threadIdx.x;
    #pragma unroll
    for (int cb = 0; cb < 3; cb++) {
        int rho = (3 * r + cb) & 65535;
        int w0 = rho, w1 = 65536 + rho, w2 = 131072 + rho;
        const __half* s0 = g_xh + (size_t)(w0 / 3) * CD + (w0 % 3) * 256;
        const __half* s1 = g_xh + (size_t)(w1 / 3) * CD + (w1 % 3) * 256;
        const __half* s2 = g_xh + (size_t)(w2 / 3) * CD + (w2 % 3) * 256;
        float red = __half2float(s0[tid]);
        float gb  = __half2float(s1[tid]) + __half2float(s2[tid]);
        size_t o = (size_t)r * CD + cb * 256 + tid;
        g_kinh[o] = __float2half_rn(red);
        g_qinh[o] = __float2half_rn(gb);
    }
}

// ---------------------------------------------------------------------------
// Kernel 3: weight-stationary fp16 GEMM  C[r,n] = sum_k A[r,k]*W[n,k] (+bias)
// W panel for one 128-col n-block over full K=768 lives in smem (192KB).
// Each CTA processes NCHUNK m-blocks, streaming A tiles (16KB double buffer).
// 512 threads, warp grid 4(m)x4(n), warp tile 32x32, mma.m16n8k16.
// smem total = 192KB (W) + 32KB (A) = 224KB -> 1 CTA/SM, 16 warps.
// ---------------------------------------------------------------------------
__device__ __forceinline__ const __half* srcSelH(int s) {
    switch (s) { case 0: return g_qinh; case 1: return g_kinh; default: return g_ath; }
}
__device__ __forceinline__ __half* dstSelH(int s) {
    switch (s) { case 0: return g_qh; case 1: return g_kh; case 2: return g_vh; default: return nullptr; }
}

__global__ __launch_bounds__(512, 1) void k_wst(int aSel, int cSel, int wOff,
                                                const float* __restrict__ bias) {
    extern __shared__ __align__(16) __half smw[];
    __half* Wp = smw;                 // 12 chunks x 8192 halves = 196608 B
    __half* Ap = smw + 98304;         // 2 stages x 8192 halves = 32768 B

    const __half* A = srcSelH(aSel);
    const __half* W = g_wh + wOff;
    __half* Ch = dstSelH(cSel);

    int tid = threadIdx.x, lane = tid & 31, wid = tid >> 5;
    int wm = wid & 3, wn = wid >> 2;
    int n0 = blockIdx.x * 128;
    int mbase = blockIdx.y * NCHUNK;
    int g  = lane >> 2, tg = lane & 3;
    int mA = lane >> 3;

    // ---- load W panel (once) -------------------------------------------------
    {
        int row = tid >> 2, q = tid & 3;
        const __half* Wr = W + (size_t)(n0 + row) * CD;
        #pragma unroll
        for (int c = 0; c < 12; c++) {
            #pragma unroll
            for (int j = 0; j < 2; j++) {
                int gr = q + 4 * j;
                int sw = gr ^ (row & 7);
                cp16(Wp + c * 8192 + row * 64 + sw * 8, Wr + c * 64 + gr * 8);
            }
        }
    }

    // A-tile fill: stage s, m-block base row m0b, k offset k0
    int frow = tid >> 2, fq = tid & 3;
    auto fillA = [&](int s, int m0b, int k0) {
        __half* As = Ap + s * 8192;
        const __half* Ar = A + (size_t)(m0b + frow) * CD + k0;
        #pragma unroll
        for (int j = 0; j < 2; j++) {
            int gr = fq + 4 * j;
            int sw = gr ^ (frow & 7);
            cp16(As + frow * 64 + sw * 8, Ar + gr * 8);
        }
    };

    // prime: W panel + first A tile -> group 0
    fillA(0, mbase * 128, 0);
    asm volatile("cp.async.commit_group;\n");

    for (int mb = 0; mb < NCHUNK; mb++) {
        int m0 = (mbase + mb) * 128;

        float acc[2][4][4];
        #pragma unroll
        for (int i = 0; i < 2; i++)
            #pragma unroll
            for (int j = 0; j < 4; j++)
                #pragma unroll
                for (int c = 0; c < 4; c++) acc[i][j][c] = 0.f;

        #pragma unroll 1
        for (int kt = 0; kt < 12; kt++) {
            int t = mb * 12 + kt;
            if (t + 1 < NCHUNK * 12) {
                int nt = t + 1;
                fillA(nt & 1, (mbase + nt / 12) * 128, (nt % 12) * 64);
                asm volatile("cp.async.commit_group;\n");
                asm volatile("cp.async.wait_group 1;\n");
            } else {
                asm volatile("cp.async.wait_group 0;\n");
            }
            __syncthreads();

            uint32_t aB = s2u(Ap + (t & 1) * 8192);
            uint32_t bB = s2u(Wp + kt * 8192);

            #pragma unroll
            for (int kc = 0; kc < 4; kc++) {
                unsigned afr[2][4];
                #pragma unroll
                for (int im = 0; im < 2; im++) {
                    int row = wm * 32 + im * 16 + (mA & 1) * 8 + (lane & 7);
                    int gr  = kc * 2 + (mA >> 1);
                    int sw  = gr ^ (row & 7);
                    ldsm4(afr[im][0], afr[im][1], afr[im][2], afr[im][3],
                          aB + (unsigned)(row * 64 + sw * 8) * 2u);
                }
                unsigned bfr[4][2];
                #pragma unroll
                for (int pr = 0; pr < 2; pr++) {
                    int n  = wn * 32 + pr * 16 + ((lane >> 4) * 8) + (lane & 7);
                    int kg = kc * 2 + ((lane >> 3) & 1);
                    int sw = kg ^ (n & 7);
                    unsigned r0, r1, r2, r3;
                    ldsm4(r0, r1, r2, r3, bB + (unsigned)(n * 64 + sw * 8) * 2u);
                    bfr[pr*2][0] = r0; bfr[pr*2][1] = r1;
                    bfr[pr*2+1][0] = r2; bfr[pr*2+1][1] = r3;
                }
                #pragma unroll
                for (int im = 0; im < 2; im++)
                    #pragma unroll
                    for (int in_ = 0; in_ < 4; in_++)
                        mma16816(acc[im][in_], afr[im], bfr[in_]);
            }
            __syncthreads();
        }

        // epilogue for this m-block (direct stores; no smem use)
        if (Ch) {
            #pragma unroll
            for (int im = 0; im < 2; im++) {
                int row = m0 + wm * 32 + im * 16 + g;
                #pragma unroll
                for (int in_ = 0; in_ < 4; in_++) {
                    int col = n0 + wn * 32 + in_ * 8 + 2 * tg;
                    *reinterpret_cast<unsigned*>(&Ch[(size_t)row * CD + col]) =
                        packh2(acc[im][in_][0], acc[im][in_][1]);
                    *reinterpret_cast<unsigned*>(&Ch[(size_t)(row + 8) * CD + col]) =
                        packh2(acc[im][in_][2], acc[im][in_][3]);
                }
            }
        } else {
            #pragma unroll
            for (int im = 0; im < 2; im++) {
                int row = m0 + wm * 32 + im * 16 + g;
                #pragma unroll
                for (int in_ = 0; in_ < 4; in_++) {
                    int col = n0 + wn * 32 + in_ * 8 + 2 * tg;
                    float b0 = bias[col], b1 = bias[col + 1];
                    *(float2*)(g_a + (size_t)row * CD + col) =
                        make_float2(acc[im][in_][0] + b0, acc[im][in_][1] + b1);
                    *(float2*)(g_a + (size_t)(row + 8) * CD + col) =
                        make_float2(acc[im][in_][2] + b0, acc[im][in_][3] + b1);
                }
            }
        }
    }
}

// ---------------------------------------------------------------------------
// Kernel 4: attention (mma.sync flash-style), block per (window, head)
// ---------------------------------------------------------------------------
__global__ __launch_bounds__(128) void k_attn() {
    __shared__ __half Qs[64 * 72], Ks[64 * 72], Vs[64 * 72];
    int win = blockIdx.x, hd = blockIdx.y;
    int r0 = win * 64, co = hd * 64;
    int tid = threadIdx.x, lane = tid & 31, wid = tid >> 5;
    int g = lane >> 2, tg = lane & 3;
    int mA = lane >> 3;

    {
        int row = tid >> 1, gp = tid & 1;
        size_t gbase = (size_t)(r0 + row) * CD + co;
        const __half* qs = g_qh + gbase;
        const __half* ks = g_kh + gbase;
        const __half* vs = g_vh + gbase;
        #pragma unroll
        for (int j = 0; j < 4; j++) {
            int gr = gp + 2 * j;
            cp16(Qs + row * 72 + gr * 8, qs + gr * 8);
            cp16(Ks + row * 72 + gr * 8, ks + gr * 8);
            cp16(Vs + row * 72 + gr * 8, vs + gr * 8);
        }
    }
    asm volatile("cp.async.commit_group;\n");
    asm volatile("cp.async.wait_group 0;\n");
    __syncthreads();

    unsigned qB = (unsigned)__cvta_generic_to_shared(Qs);
    unsigned kB = (unsigned)__cvta_generic_to_shared(Ks);
    unsigned vB = (unsigned)__cvta_generic_to_shared(Vs);

    float sc[8][4];
    #pragma unroll
    for (int j = 0; j < 8; j++)
        #pragma unroll
        for (int c = 0; c < 4; c++) sc[j][c] = 0.f;

    #pragma unroll
    for (int kc = 0; kc < 4; kc++) {
        unsigned afr[4];
        {
            int rr = wid * 16 + (mA & 1) * 8 + (lane & 7);
            ldsm4(afr[0], afr[1], afr[2], afr[3],
                  qB + (unsigned)(rr * 72 + kc * 16 + (mA >> 1) * 8) * 2u);
        }
        unsigned bfr[8][2];
        #pragma unroll
        for (int pr = 0; pr < 4; pr++) {
            int n = pr * 16 + ((lane >> 4) * 8) + (lane & 7);
            unsigned r0_, r1_, r2_, r3_;
            ldsm4(r0_, r1_, r2_, r3_,
                  kB + (unsigned)(n * 72 + kc * 16 + ((lane >> 3) & 1) * 8) * 2u);
            bfr[pr*2][0] = r0_; bfr[pr*2][1] = r1_;
            bfr[pr*2+1][0] = r2_; bfr[pr*2+1][1] = r3_;
        }
        #pragma unroll
        for (int in_ = 0; in_ < 8; in_++)
            mma16816(sc[in_], afr, bfr[in_]);
    }

    const float scale = 0.125f;
    float m0 = -1e30f, m1 = -1e30f;
    #pragma unroll
    for (int j = 0; j < 8; j++) {
        sc[j][0] *= scale; sc[j][1] *= scale; sc[j][2] *= scale; sc[j][3] *= scale;
        m0 = fmaxf(m0, fmaxf(sc[j][0], sc[j][1]));
        m1 = fmaxf(m1, fmaxf(sc[j][2], sc[j][3]));
    }
    #pragma unroll
    for (int o = 1; o < 4; o <<= 1) {
        m0 = fmaxf(m0, __shfl_xor_sync(0xffffffffu, m0, o));
        m1 = fmaxf(m1, __shfl_xor_sync(0xffffffffu, m1, o));
    }
    float s0 = 0.f, s1 = 0.f;
    #pragma unroll
    for (int j = 0; j < 8; j++) {
        sc[j][0] = __expf(sc[j][0] - m0); sc[j][1] = __expf(sc[j][1] - m0);
        sc[j][2] = __expf(sc[j][2] - m1); sc[j][3] = __expf(sc[j][3] - m1);
        s0 += sc[j][0] + sc[j][1];
        s1 += sc[j][2] + sc[j][3];
    }
    #pragma unroll
    for (int o = 1; o < 4; o <<= 1) {
        s0 += __shfl_xor_sync(0xffffffffu, s0, o);
        s1 += __shfl_xor_sync(0xffffffffu, s1, o);
    }
    float i0 = 1.f / s0, i1 = 1.f / s1;
    unsigned p0[8], p1[8];
    #pragma unroll
    for (int j = 0; j < 8; j++) {
        p0[j] = packh2(sc[j][0] * i0, sc[j][1] * i0);
        p1[j] = packh2(sc[j][2] * i1, sc[j][3] * i1);
    }

    float oc[8][4];
    #pragma unroll
    for (int j = 0; j < 8; j++)
        #pragma unroll
        for (int c = 0; c < 4; c++) oc[j][c] = 0.f;

    #pragma unroll
    for (int kc = 0; kc < 4; kc++) {
        unsigned afr[4] = { p0[2*kc], p1[2*kc], p0[2*kc+1], p1[2*kc+1] };
        unsigned bfr[8][2];
        #pragma unroll
        for (int pr = 0; pr < 4; pr++) {
            int t = kc * 16 + (lane & 7) + 8 * ((lane >> 3) & 1);
            int n = pr * 16 + 8 * (lane >> 4);
            unsigned r0_, r1_, r2_, r3_;
            ldsm4t(r0_, r1_, r2_, r3_, vB + (unsigned)(t * 72 + n) * 2u);
            bfr[pr*2][0] = r0_; bfr[pr*2][1] = r1_;
            bfr[pr*2+1][0] = r2_; bfr[pr*2+1][1] = r3_;
        }
        #pragma unroll
        for (int in_ = 0; in_ < 8; in_++)
            mma16816(oc[in_], afr, bfr[in_]);
    }

    int rowA = r0 + wid * 16 + g;
    #pragma unroll
    for (int in_ = 0; in_ < 8; in_++) {
        int col = co + in_ * 8 + 2 * tg;
        *reinterpret_cast<unsigned*>(&g_ath[(size_t)rowA * CD + col])       = packh2(oc[in_][0], oc[in_][1]);
        *reinterpret_cast<unsigned*>(&g_ath[(size_t)(rowA + 8) * CD + col]) = packh2(oc[in_][2], oc[in_][3]);
    }
}

// ---------------------------------------------------------------------------
// Kernel 5: fused LN2 + MLP (hidden dim 1 -> rank-1 output). fp32 in/out.
// ---------------------------------------------------------------------------
__global__ void k_final(const float* __restrict__ n2g, const float* __restrict__ n2b,
                        const float* __restrict__ f1w, const float* __restrict__ f1b,
                        const float* __restrict__ f2w, const float* __restrict__ f2b,
                        float* __restrict__ out) {
    int r = blockIdx.x;
    const float* a = g_a + (size_t)r * CD;
    int tid = threadIdx.x;
    float s1 = 0.f, s2 = 0.f, s3 = 0.f, s4 = 0.f, s5 = 0.f;
    #pragma unroll
    for (int u = 0; u < 3; u++) {
        int c = tid + 256 * u;
        float x = a[c];
        float wt = n2g[c] * f1w[c];
        s1 += x; s2 += x * x; s3 += x * wt; s4 += wt; s5 += n2b[c] * f1w[c];
    }
    #pragma unroll
    for (int o = 16; o > 0; o >>= 1) {
        s1 += __shfl_xor_sync(0xffffffffu, s1, o);
        s2 += __shfl_xor_sync(0xffffffffu, s2, o);
        s3 += __shfl_xor_sync(0xffffffffu, s3, o);
        s4 += __shfl_xor_sync(0xffffffffu, s4, o);
        s5 += __shfl_xor_sync(0xffffffffu, s5, o);
    }
    __shared__ float sh[8][5];
    int wid = tid >> 5;
    if ((tid & 31) == 0) {
        sh[wid][0]=s1; sh[wid][1]=s2; sh[wid][2]=s3; sh[wid][3]=s4; sh[wid][4]=s5;
    }
    __syncthreads();
    float S1=0.f,S2=0.f,S3=0.f,S4=0.f,S5=0.f;
    #pragma unroll
    for (int k = 0; k < 8; k++) {
        S1+=sh[k][0]; S2+=sh[k][1]; S3+=sh[k][2]; S4+=sh[k][3]; S5+=sh[k][4];
    }
    float m   = S1 * (1.f / 768.f);
    float var = S2 * (1.f / 768.f) - m * m;
    float inv = rsqrtf(var + EPS);
    float s   = (S3 - m * S4) * inv + S5 + f1b[0];
    float hdn = 0.5f * s * (1.f + erff(s * 0.70710678118654752f));

    float* o = out + (size_t)r * CD;
    #pragma unroll
    for (int u = 0; u < 3; u++) {
        int c = tid + 256 * u;
        o[c] = hdn * f2w[c] + f2b[c];
    }
}

// ---------------------------------------------------------------------------
extern "C" void kernel_launch(void* const* d_in, const int* in_sizes, int n_in,
                              void* d_out, int out_size) {
    const float* x     = (const float*)d_in[0];
    const float* n1g   = (const float*)d_in[1];
    const float* n1b   = (const float*)d_in[2];
    const float* n2g   = (const float*)d_in[3];
    const float* n2b   = (const float*)d_in[4];
    const float* qkvw  = (const float*)d_in[5];
    const float* projw = (const float*)d_in[6];
    const float* projb = (const float*)d_in[7];
    const float* f1w   = (const float*)d_in[8];
    const float* f1b   = (const float*)d_in[9];
    const float* f2w   = (const float*)d_in[10];
    const float* f2b   = (const float*)d_in[11];
    float* out = (float*)d_out;

    const int WST_SMEM = (98304 + 16384) * 2;   // 229376 bytes
    cudaFuncSetAttribute(k_wst, cudaFuncAttributeMaxDynamicSharedMemorySize, WST_SMEM);

    k_w2h<<<9216, 256>>>(qkvw, projw);
    k_ln1<<<RTOT, 256>>>(x, n1g, n1b);
    k_gather<<<RTOT, 256>>>();

    dim3 gg(6, 64);
    k_wst<<<gg, 512, WST_SMEM>>>(0, 0, 0,          nullptr);  // Q
    k_wst<<<gg, 512, WST_SMEM>>>(1, 1, 589824,     nullptr);  // K
    k_wst<<<gg, 512, WST_SMEM>>>(1, 2, 2 * 589824, nullptr);  // V

    k_attn<<<dim3(1024, 12), 128>>>();

    k_wst<<<gg, 512, WST_SMEM>>>(2, 3, 3 * 589824, projb);    // proj -> g_a (fp32)

    k_final<<<RTOT, 256>>>(n2g, n2b, f1w, f1b, f2w, f2b, out);
}